// round 4
// baseline (speedup 1.0000x reference)
#include <cuda_runtime.h>

// ---------------- Problem constants ----------------
#define NB    8
#define SD    512
#define CIN   512
#define COUT  512
#define CPG   64      // channels per group
#define NG    8       // groups
#define HH    64
#define WW    64
#define HWSZ  4096
#define KDK   4608    // 512*9 (im2col K for dk conv)
#define ODK   32768   // C_OUT * 64
#define NCOL  72      // 8 batches * 9 spatial
#define NCOLP 80      // padded to even multiple for f32x2 pairing

// ---------------- Device scratch (no allocs allowed) ----------------
__device__ float g_pooled[NB * SD];            // 16 KB
__device__ float g_pwkn[NB * ODK];             // 1 MB
__device__ float g_pwbias[NB * COUT];          // 16 KB
__device__ float g_B[KDK * NCOLP];             // 1.47 MB im2col of style
__device__ float g_dwT[NB * CPG * 9 * COUT];   // 9.44 MB dynamic depthwise weights, [n][ci][k][co]

// ---------------- f32x2 helpers (Blackwell packed fp32) ----------------
__device__ __forceinline__ unsigned long long pk2(float lo, float hi) {
    unsigned long long r;
    asm("mov.b64 %0, {%1, %2};" : "=l"(r) : "f"(lo), "f"(hi));
    return r;
}
__device__ __forceinline__ void upk2(unsigned long long v, float& lo, float& hi) {
    asm("mov.b64 {%0, %1}, %2;" : "=f"(lo), "=f"(hi) : "l"(v));
}
__device__ __forceinline__ void fma2(unsigned long long& d, unsigned long long a, unsigned long long b) {
    asm("fma.rn.f32x2 %0, %1, %2, %0;" : "+l"(d) : "l"(a), "l"(b));
}

// ---------------- K0: 3x3 avg pool of style (window at origin) ----------------
__global__ void k_pool(const float* __restrict__ style) {
    int i = blockIdx.x * blockDim.x + threadIdx.x;
    if (i >= NB * SD) return;
    const float* p = style + (size_t)i * 25;
    float s = 0.f;
#pragma unroll
    for (int y = 0; y < 3; y++)
#pragma unroll
        for (int x = 0; x < 3; x++)
            s += p[y * 5 + x];
    g_pooled[i] = s * (1.0f / 9.0f);
}

// ---------------- K0b: build im2col B matrix [K][80] (cols 72..79 zero) ----------------
__global__ void k_buildB(const float* __restrict__ style) {
    int i = blockIdx.x * blockDim.x + threadIdx.x;
    if (i >= KDK * NCOLP) return;
    int k = i / NCOLP, c = i % NCOLP;
    float v = 0.f;
    if (c < NCOL) {
        int n = c / 9, q = c % 9, y = q / 3, x = q % 3;
        int s = k / 9, r = k % 9, dy = r / 3, dx = r % 3;
        v = style[((size_t)(n * SD + s) * 5 + (y + dy)) * 5 + (x + dx)];
    }
    g_B[i] = v;
}

// ---------------- K1: pooled GEMVs -> pw_kn (32768 rows) and pw_bias (512 rows) ----------------
__global__ void __launch_bounds__(256) k_pw(const float* __restrict__ Wpwk, const float* __restrict__ bpwk,
                                            const float* __restrict__ Wpwb, const float* __restrict__ bpwb) {
    __shared__ float ps[NB * SD];
    int tid = threadIdx.x;
    for (int i = tid; i < NB * SD; i += 256) ps[i] = g_pooled[i];
    __syncthreads();

    int r = blockIdx.x * 256 + tid;
    if (r >= ODK + COUT) return;
    bool isk = (r < ODK);
    int rr = isk ? r : (r - ODK);
    const float* w = isk ? (Wpwk + (size_t)r * SD) : (Wpwb + (size_t)rr * SD);
    float bias = isk ? bpwk[r] : bpwb[rr];

    float acc[NB];
#pragma unroll
    for (int n = 0; n < NB; n++) acc[n] = 0.f;

    for (int s = 0; s < SD; s += 4) {
        float4 wv = *(const float4*)(w + s);
#pragma unroll
        for (int n = 0; n < NB; n++) {
            const float* pp = &ps[n * SD + s];
            acc[n] += wv.x * pp[0] + wv.y * pp[1] + wv.z * pp[2] + wv.w * pp[3];
        }
    }
    if (isk) {
#pragma unroll
        for (int n = 0; n < NB; n++) g_pwkn[(size_t)n * ODK + r] = acc[n] + bias;
    } else {
#pragma unroll
        for (int n = 0; n < NB; n++) g_pwbias[n * COUT + rr] = acc[n] + bias;
    }
}

// ---------------- K2: dk GEMM (32768 x 72 x 4608) with f32x2 ----------------
// A = W_dk [m][k] streamed once; B in smem; output scattered into g_dwT + b_dk.
#define MT 128
#define KT 32
#define AS_STRIDE 132

__global__ void __launch_bounds__(256) k_dk(const float* __restrict__ Wdk, const float* __restrict__ bdk) {
    __shared__ __align__(16) float As[KT * AS_STRIDE];
    __shared__ __align__(16) float Bs[KT * NCOLP];

    int tid = threadIdx.x;
    int m0 = blockIdx.x * MT;
    int mt = tid & 31;   // m sub-tile: rows mt*4 .. mt*4+3
    int nt = tid >> 5;   // 0..7: cols nt*10 .. nt*10+9 (5 f32x2 pairs)

    unsigned long long acc[4][5];
#pragma unroll
    for (int i = 0; i < 4; i++)
#pragma unroll
        for (int j = 0; j < 5; j++) acc[i][j] = 0ULL;

    int ml = tid >> 3;  // 0..31 (A-load row)
    int kq = tid & 7;   // 0..7  (A-load k quad)

    for (int k0 = 0; k0 < KDK; k0 += KT) {
        // Load A tile (128 x 32), transposed into As[k][m]
#pragma unroll
        for (int p = 0; p < 4; p++) {
            int m = ml + 32 * p;
            float4 a = *(const float4*)(Wdk + (size_t)(m0 + m) * KDK + k0 + kq * 4);
            As[(kq * 4 + 0) * AS_STRIDE + m] = a.x;
            As[(kq * 4 + 1) * AS_STRIDE + m] = a.y;
            As[(kq * 4 + 2) * AS_STRIDE + m] = a.z;
            As[(kq * 4 + 3) * AS_STRIDE + m] = a.w;
        }
        // Load B tile (32 x 80)
        for (int i = tid; i < KT * NCOLP; i += 256)
            Bs[i] = g_B[(size_t)k0 * NCOLP + i];
        __syncthreads();

#pragma unroll 8
        for (int kk = 0; kk < KT; kk++) {
            float4 a = *(const float4*)(&As[kk * AS_STRIDE + mt * 4]);
            unsigned long long ad[4];
            ad[0] = pk2(a.x, a.x);
            ad[1] = pk2(a.y, a.y);
            ad[2] = pk2(a.z, a.z);
            ad[3] = pk2(a.w, a.w);
            const float* brow = &Bs[kk * NCOLP + nt * 10];
            unsigned long long b[5];
#pragma unroll
            for (int j = 0; j < 5; j++) b[j] = *(const unsigned long long*)(brow + 2 * j);
#pragma unroll
            for (int i = 0; i < 4; i++)
#pragma unroll
                for (int j = 0; j < 5; j++) fma2(acc[i][j], ad[i], b[j]);
        }
        __syncthreads();
    }

    // Scatter results: dwT[n][ci][kidx][co] = dk + b_dk[o], o = co*64 + ci
#pragma unroll
    for (int i = 0; i < 4; i++) {
        int o = m0 + mt * 4 + i;
        float bv = bdk[o];
        int co = o >> 6, ci = o & 63;
#pragma unroll
        for (int j = 0; j < 5; j++) {
            float lo, hi;
            upk2(acc[i][j], lo, hi);
            int c0 = nt * 10 + 2 * j;
            if (c0 < NCOL) {
                int n = c0 / 9, kidx = c0 % 9;
                g_dwT[((size_t)((n * CPG + ci) * 9 + kidx)) * COUT + co] = lo + bv;
            }
            int c1 = c0 + 1;
            if (c1 < NCOL) {
                int n = c1 / 9, kidx = c1 % 9;
                g_dwT[((size_t)((n * CPG + ci) * 9 + kidx)) * COUT + co] = hi + bv;
            }
        }
    }
}

// ---------------- K3: fused reflect-pad + grouped depthwise 3x3 + grouped pointwise + bias ----
// Block = (n, g, rowblock of 4 rows). 256 threads: thread = (co in 0..63, hl in 0..3).
// depth tile kept in smem; no global intermediate.
#define SMEM_CONV ((CPG * 4 * WW + 6 * 68) * 4)

__device__ __forceinline__ int refl(int i) {
    return i < 0 ? -i : (i > 63 ? 126 - i : i);
}

__global__ void __launch_bounds__(256) k_conv(const float* __restrict__ pred, float* __restrict__ out) {
    extern __shared__ __align__(16) float sm[];
    float* depth_s = sm;                    // [co][hl][w] : 64*4*64
    float* in_s = sm + CPG * 4 * WW;        // [6][68] padded rows of current input channel

    int tid = threadIdx.x;
    int co = tid & 63;
    int hl = tid >> 6;
    int rb = blockIdx.x, g = blockIdx.y, n = blockIdx.z;
    int h0 = rb * 4;

    const float* base = pred + (size_t)(n * CIN + g * CPG) * HWSZ;

    float acc[64];
#pragma unroll
    for (int w = 0; w < 64; w++) acc[w] = 0.f;

    for (int ci = 0; ci < CPG; ci++) {
        const float* plane = base + (size_t)ci * HWSZ;
        // cooperative load of 6 reflect-padded rows (cols 0..65 valid)
        for (int i = tid; i < 6 * 68; i += 256) {
            int r = i / 68, c = i % 68;
            float v = 0.f;
            if (c < 66) {
                int orow = refl(h0 + r - 1);
                int ocol = refl(c - 1);
                v = plane[orow * WW + ocol];
            }
            in_s[r * 68 + c] = v;
        }
        __syncthreads();

        // per-thread 3x3 weights for (n, co_global, ci): dwT[n][ci][k][co_global]
        const float* wp = g_dwT + ((size_t)((n * CPG + ci) * 9)) * COUT + (g * CPG + co);
        float dreg[9];
#pragma unroll
        for (int k = 0; k < 9; k++) dreg[k] = wp[k * COUT];

#pragma unroll
        for (int kh = 0; kh < 3; kh++) {
            const float* row = &in_s[(hl + kh) * 68];
            float wa = dreg[kh * 3 + 0];
            float wb = dreg[kh * 3 + 1];
            float wc = dreg[kh * 3 + 2];
#pragma unroll
            for (int c0 = 0; c0 < 64; c0 += 16) {
                float buf[18];
                float4 t0 = *(const float4*)(row + c0);
                float4 t1 = *(const float4*)(row + c0 + 4);
                float4 t2 = *(const float4*)(row + c0 + 8);
                float4 t3 = *(const float4*)(row + c0 + 12);
                buf[0] = t0.x;  buf[1] = t0.y;  buf[2] = t0.z;  buf[3] = t0.w;
                buf[4] = t1.x;  buf[5] = t1.y;  buf[6] = t1.z;  buf[7] = t1.w;
                buf[8] = t2.x;  buf[9] = t2.y;  buf[10] = t2.z; buf[11] = t2.w;
                buf[12] = t3.x; buf[13] = t3.y; buf[14] = t3.z; buf[15] = t3.w;
                buf[16] = row[c0 + 16];
                buf[17] = row[c0 + 17];
#pragma unroll
                for (int i2 = 0; i2 < 16; i2++)
                    acc[c0 + i2] += buf[i2] * wa + buf[i2 + 1] * wb + buf[i2 + 2] * wc;
            }
        }
        __syncthreads();  // before next ci overwrites in_s
    }

    // stash depth tile in smem: depth_s[(co*4 + hl)*64 + w]
    {
        float* dst = depth_s + (co * 4 + hl) * 64;
#pragma unroll
        for (int w = 0; w < 64; w += 4)
            *(float4*)(dst + w) = make_float4(acc[w], acc[w + 1], acc[w + 2], acc[w + 3]);
    }
    __syncthreads();

    // pointwise: out[co] = sum_cm pw_kn[n][co_global][cm] * depth[cm] + pw_bias
    const float* pwrow = g_pwkn + (size_t)n * ODK + (g * CPG + co) * 64;
#pragma unroll
    for (int w = 0; w < 64; w++) acc[w] = 0.f;  // reuse regs as output accumulators
    for (int cm = 0; cm < 64; cm++) {
        float v = pwrow[cm];
        const float* ds = depth_s + (cm * 4 + hl) * 64;
#pragma unroll
        for (int w = 0; w < 64; w += 4) {
            float4 t = *(const float4*)(ds + w);  // broadcast across warp
            acc[w]     += v * t.x;
            acc[w + 1] += v * t.y;
            acc[w + 2] += v * t.z;
            acc[w + 3] += v * t.w;
        }
    }

    float bias = g_pwbias[n * COUT + g * CPG + co];
    float* op = out + (((size_t)(n * COUT + g * CPG + co)) * HH + (h0 + hl)) * WW;
#pragma unroll
    for (int w = 0; w < 64; w += 4)
        *(float4*)(op + w) = make_float4(acc[w] + bias, acc[w + 1] + bias, acc[w + 2] + bias, acc[w + 3] + bias);
}

// ---------------- Launch ----------------
extern "C" void kernel_launch(void* const* d_in, const int* in_sizes, int n_in,
                              void* d_out, int out_size) {
    const float* style = (const float*)d_in[0];
    const float* pred  = (const float*)d_in[1];
    const float* Wdk   = (const float*)d_in[2];
    const float* bdk   = (const float*)d_in[3];
    const float* Wpwk  = (const float*)d_in[4];
    const float* bpwk  = (const float*)d_in[5];
    const float* Wpwb  = (const float*)d_in[6];
    const float* bpwb  = (const float*)d_in[7];
    float* out = (float*)d_out;

    cudaFuncSetAttribute(k_conv, cudaFuncAttributeMaxDynamicSharedMemorySize, SMEM_CONV);

    k_pool<<<(NB * SD + 255) / 256, 256>>>(style);
    k_buildB<<<(KDK * NCOLP + 255) / 256, 256>>>(style);
    k_pw<<<(ODK + COUT + 255) / 256, 256>>>(Wpwk, bpwk, Wpwb, bpwb);
    k_dk<<<ODK / MT, 256>>>(Wdk, bdk);
    k_conv<<<dim3(HH / 4, NG, NB), 256, SMEM_CONV>>>(pred, out);
}

// round 5
// speedup vs baseline: 1.0018x; 1.0018x over previous
#include <cuda_runtime.h>

// ---------------- Problem constants ----------------
#define NB    8
#define SD    512
#define CIN   512
#define COUT  512
#define CPG   64      // channels per group
#define NG    8       // groups
#define HH    64
#define WW    64
#define HWSZ  4096
#define KDK   4608    // 512*9 (im2col K for dk conv)
#define ODK   32768   // C_OUT * 64
#define NCOL  72      // 8 batches * 9 spatial
#define NCOLP 80      // padded to even multiple for f32x2 pairing

// ---------------- Device scratch (no allocs allowed) ----------------
__device__ float g_pooled[NB * SD];            // 16 KB
__device__ float g_pwkn[NB * ODK];             // 1 MB
__device__ float g_pwbias[NB * COUT];          // 16 KB
__device__ float g_B[KDK * NCOLP];             // 1.47 MB im2col of style
__device__ float g_dwT[NB * CPG * 9 * COUT];   // 9.44 MB dynamic depthwise weights, [n][ci][k][co]

// ---------------- f32x2 helpers (Blackwell packed fp32) ----------------
__device__ __forceinline__ unsigned long long pk2(float lo, float hi) {
    unsigned long long r;
    asm("mov.b64 %0, {%1, %2};" : "=l"(r) : "f"(lo), "f"(hi));
    return r;
}
__device__ __forceinline__ void upk2(unsigned long long v, float& lo, float& hi) {
    asm("mov.b64 {%0, %1}, %2;" : "=f"(lo), "=f"(hi) : "l"(v));
}
__device__ __forceinline__ void fma2(unsigned long long& d, unsigned long long a, unsigned long long b) {
    asm("fma.rn.f32x2 %0, %1, %2, %0;" : "+l"(d) : "l"(a), "l"(b));
}

// ---------------- K0: 3x3 avg pool of style (window at origin) ----------------
__global__ void k_pool(const float* __restrict__ style) {
    int i = blockIdx.x * blockDim.x + threadIdx.x;
    if (i >= NB * SD) return;
    const float* p = style + (size_t)i * 25;
    float s = 0.f;
#pragma unroll
    for (int y = 0; y < 3; y++)
#pragma unroll
        for (int x = 0; x < 3; x++)
            s += p[y * 5 + x];
    g_pooled[i] = s * (1.0f / 9.0f);
}

// ---------------- K0b: build im2col B matrix [K][80] (cols 72..79 zero) ----------------
__global__ void k_buildB(const float* __restrict__ style) {
    int i = blockIdx.x * blockDim.x + threadIdx.x;
    if (i >= KDK * NCOLP) return;
    int k = i / NCOLP, c = i % NCOLP;
    float v = 0.f;
    if (c < NCOL) {
        int n = c / 9, q = c % 9, y = q / 3, x = q % 3;
        int s = k / 9, r = k % 9, dy = r / 3, dx = r % 3;
        v = style[((size_t)(n * SD + s) * 5 + (y + dy)) * 5 + (x + dx)];
    }
    g_B[i] = v;
}

// ---------------- K1: pooled GEMVs -> pw_kn (32768 rows) and pw_bias (512 rows) ----------------
__global__ void __launch_bounds__(256) k_pw(const float* __restrict__ Wpwk, const float* __restrict__ bpwk,
                                            const float* __restrict__ Wpwb, const float* __restrict__ bpwb) {
    __shared__ float ps[NB * SD];
    int tid = threadIdx.x;
    for (int i = tid; i < NB * SD; i += 256) ps[i] = g_pooled[i];
    __syncthreads();

    int r = blockIdx.x * 256 + tid;
    if (r >= ODK + COUT) return;
    bool isk = (r < ODK);
    int rr = isk ? r : (r - ODK);
    const float* w = isk ? (Wpwk + (size_t)r * SD) : (Wpwb + (size_t)rr * SD);
    float bias = isk ? bpwk[r] : bpwb[rr];

    float acc[NB];
#pragma unroll
    for (int n = 0; n < NB; n++) acc[n] = 0.f;

    for (int s = 0; s < SD; s += 4) {
        float4 wv = *(const float4*)(w + s);
#pragma unroll
        for (int n = 0; n < NB; n++) {
            const float* pp = &ps[n * SD + s];
            acc[n] += wv.x * pp[0] + wv.y * pp[1] + wv.z * pp[2] + wv.w * pp[3];
        }
    }
    if (isk) {
#pragma unroll
        for (int n = 0; n < NB; n++) g_pwkn[(size_t)n * ODK + r] = acc[n] + bias;
    } else {
#pragma unroll
        for (int n = 0; n < NB; n++) g_pwbias[n * COUT + rr] = acc[n] + bias;
    }
}

// ---------------- K2: dk GEMM (32768 x 72 x 4608) with f32x2 ----------------
// A = W_dk [m][k] streamed once; B in smem; output scattered into g_dwT + b_dk.
#define MT 128
#define KT 32
#define AS_STRIDE 132

__global__ void __launch_bounds__(256) k_dk(const float* __restrict__ Wdk, const float* __restrict__ bdk) {
    __shared__ __align__(16) float As[KT * AS_STRIDE];
    __shared__ __align__(16) float Bs[KT * NCOLP];

    int tid = threadIdx.x;
    int m0 = blockIdx.x * MT;
    int mt = tid & 31;   // m sub-tile: rows mt*4 .. mt*4+3
    int nt = tid >> 5;   // 0..7: cols nt*10 .. nt*10+9 (5 f32x2 pairs)

    unsigned long long acc[4][5];
#pragma unroll
    for (int i = 0; i < 4; i++)
#pragma unroll
        for (int j = 0; j < 5; j++) acc[i][j] = 0ULL;

    int ml = tid >> 3;  // 0..31 (A-load row)
    int kq = tid & 7;   // 0..7  (A-load k quad)

    for (int k0 = 0; k0 < KDK; k0 += KT) {
        // Load A tile (128 x 32), transposed into As[k][m]
#pragma unroll
        for (int p = 0; p < 4; p++) {
            int m = ml + 32 * p;
            float4 a = *(const float4*)(Wdk + (size_t)(m0 + m) * KDK + k0 + kq * 4);
            As[(kq * 4 + 0) * AS_STRIDE + m] = a.x;
            As[(kq * 4 + 1) * AS_STRIDE + m] = a.y;
            As[(kq * 4 + 2) * AS_STRIDE + m] = a.z;
            As[(kq * 4 + 3) * AS_STRIDE + m] = a.w;
        }
        // Load B tile (32 x 80)
        for (int i = tid; i < KT * NCOLP; i += 256)
            Bs[i] = g_B[(size_t)k0 * NCOLP + i];
        __syncthreads();

#pragma unroll 8
        for (int kk = 0; kk < KT; kk++) {
            float4 a = *(const float4*)(&As[kk * AS_STRIDE + mt * 4]);
            unsigned long long ad[4];
            ad[0] = pk2(a.x, a.x);
            ad[1] = pk2(a.y, a.y);
            ad[2] = pk2(a.z, a.z);
            ad[3] = pk2(a.w, a.w);
            const float* brow = &Bs[kk * NCOLP + nt * 10];
            unsigned long long b[5];
#pragma unroll
            for (int j = 0; j < 5; j++) b[j] = *(const unsigned long long*)(brow + 2 * j);
#pragma unroll
            for (int i = 0; i < 4; i++)
#pragma unroll
                for (int j = 0; j < 5; j++) fma2(acc[i][j], ad[i], b[j]);
        }
        __syncthreads();
    }

    // Scatter results: dwT[n][ci][kidx][co] = dk + b_dk[o], o = co*64 + ci
#pragma unroll
    for (int i = 0; i < 4; i++) {
        int o = m0 + mt * 4 + i;
        float bv = bdk[o];
        int co = o >> 6, ci = o & 63;
#pragma unroll
        for (int j = 0; j < 5; j++) {
            float lo, hi;
            upk2(acc[i][j], lo, hi);
            int c0 = nt * 10 + 2 * j;
            if (c0 < NCOL) {
                int n = c0 / 9, kidx = c0 % 9;
                g_dwT[((size_t)((n * CPG + ci) * 9 + kidx)) * COUT + co] = lo + bv;
            }
            int c1 = c0 + 1;
            if (c1 < NCOL) {
                int n = c1 / 9, kidx = c1 % 9;
                g_dwT[((size_t)((n * CPG + ci) * 9 + kidx)) * COUT + co] = hi + bv;
            }
        }
    }
}

// ---------------- K3: fused reflect-pad + grouped depthwise 3x3 + grouped pointwise + bias ----
// Block = (n, g, rowblock of 4 rows). 256 threads: thread = (co in 0..63, hl in 0..3).
// depth tile kept in smem; no global intermediate.
#define SMEM_CONV ((CPG * 4 * WW + 6 * 68) * 4)

__device__ __forceinline__ int refl(int i) {
    return i < 0 ? -i : (i > 63 ? 126 - i : i);
}

__global__ void __launch_bounds__(256) k_conv(const float* __restrict__ pred, float* __restrict__ out) {
    extern __shared__ __align__(16) float sm[];
    float* depth_s = sm;                    // [co][hl][w] : 64*4*64
    float* in_s = sm + CPG * 4 * WW;        // [6][68] padded rows of current input channel

    int tid = threadIdx.x;
    int co = tid & 63;
    int hl = tid >> 6;
    int rb = blockIdx.x, g = blockIdx.y, n = blockIdx.z;
    int h0 = rb * 4;

    const float* base = pred + (size_t)(n * CIN + g * CPG) * HWSZ;

    float acc[64];
#pragma unroll
    for (int w = 0; w < 64; w++) acc[w] = 0.f;

    for (int ci = 0; ci < CPG; ci++) {
        const float* plane = base + (size_t)ci * HWSZ;
        // cooperative load of 6 reflect-padded rows (cols 0..65 valid)
        for (int i = tid; i < 6 * 68; i += 256) {
            int r = i / 68, c = i % 68;
            float v = 0.f;
            if (c < 66) {
                int orow = refl(h0 + r - 1);
                int ocol = refl(c - 1);
                v = plane[orow * WW + ocol];
            }
            in_s[r * 68 + c] = v;
        }
        __syncthreads();

        // per-thread 3x3 weights for (n, co_global, ci): dwT[n][ci][k][co_global]
        const float* wp = g_dwT + ((size_t)((n * CPG + ci) * 9)) * COUT + (g * CPG + co);
        float dreg[9];
#pragma unroll
        for (int k = 0; k < 9; k++) dreg[k] = wp[k * COUT];

#pragma unroll
        for (int kh = 0; kh < 3; kh++) {
            const float* row = &in_s[(hl + kh) * 68];
            float wa = dreg[kh * 3 + 0];
            float wb = dreg[kh * 3 + 1];
            float wc = dreg[kh * 3 + 2];
#pragma unroll
            for (int c0 = 0; c0 < 64; c0 += 16) {
                float buf[18];
                float4 t0 = *(const float4*)(row + c0);
                float4 t1 = *(const float4*)(row + c0 + 4);
                float4 t2 = *(const float4*)(row + c0 + 8);
                float4 t3 = *(const float4*)(row + c0 + 12);
                buf[0] = t0.x;  buf[1] = t0.y;  buf[2] = t0.z;  buf[3] = t0.w;
                buf[4] = t1.x;  buf[5] = t1.y;  buf[6] = t1.z;  buf[7] = t1.w;
                buf[8] = t2.x;  buf[9] = t2.y;  buf[10] = t2.z; buf[11] = t2.w;
                buf[12] = t3.x; buf[13] = t3.y; buf[14] = t3.z; buf[15] = t3.w;
                buf[16] = row[c0 + 16];
                buf[17] = row[c0 + 17];
#pragma unroll
                for (int i2 = 0; i2 < 16; i2++)
                    acc[c0 + i2] += buf[i2] * wa + buf[i2 + 1] * wb + buf[i2 + 2] * wc;
            }
        }
        __syncthreads();  // before next ci overwrites in_s
    }

    // stash depth tile in smem: depth_s[(co*4 + hl)*64 + w]
    {
        float* dst = depth_s + (co * 4 + hl) * 64;
#pragma unroll
        for (int w = 0; w < 64; w += 4)
            *(float4*)(dst + w) = make_float4(acc[w], acc[w + 1], acc[w + 2], acc[w + 3]);
    }
    __syncthreads();

    // pointwise: out[co] = sum_cm pw_kn[n][co_global][cm] * depth[cm] + pw_bias
    const float* pwrow = g_pwkn + (size_t)n * ODK + (g * CPG + co) * 64;
#pragma unroll
    for (int w = 0; w < 64; w++) acc[w] = 0.f;  // reuse regs as output accumulators
    for (int cm = 0; cm < 64; cm++) {
        float v = pwrow[cm];
        const float* ds = depth_s + (cm * 4 + hl) * 64;
#pragma unroll
        for (int w = 0; w < 64; w += 4) {
            float4 t = *(const float4*)(ds + w);  // broadcast across warp
            acc[w]     += v * t.x;
            acc[w + 1] += v * t.y;
            acc[w + 2] += v * t.z;
            acc[w + 3] += v * t.w;
        }
    }

    float bias = g_pwbias[n * COUT + g * CPG + co];
    float* op = out + (((size_t)(n * COUT + g * CPG + co)) * HH + (h0 + hl)) * WW;
#pragma unroll
    for (int w = 0; w < 64; w += 4)
        *(float4*)(op + w) = make_float4(acc[w] + bias, acc[w + 1] + bias, acc[w + 2] + bias, acc[w + 3] + bias);
}

// ---------------- Launch ----------------
extern "C" void kernel_launch(void* const* d_in, const int* in_sizes, int n_in,
                              void* d_out, int out_size) {
    const float* style = (const float*)d_in[0];
    const float* pred  = (const float*)d_in[1];
    const float* Wdk   = (const float*)d_in[2];
    const float* bdk   = (const float*)d_in[3];
    const float* Wpwk  = (const float*)d_in[4];
    const float* bpwk  = (const float*)d_in[5];
    const float* Wpwb  = (const float*)d_in[6];
    const float* bpwb  = (const float*)d_in[7];
    float* out = (float*)d_out;

    cudaFuncSetAttribute(k_conv, cudaFuncAttributeMaxDynamicSharedMemorySize, SMEM_CONV);

    k_pool<<<(NB * SD + 255) / 256, 256>>>(style);
    k_buildB<<<(KDK * NCOLP + 255) / 256, 256>>>(style);
    k_pw<<<(ODK + COUT + 255) / 256, 256>>>(Wpwk, bpwk, Wpwb, bpwb);
    k_dk<<<ODK / MT, 256>>>(Wdk, bdk);
    k_conv<<<dim3(HH / 4, NG, NB), 256, SMEM_CONV>>>(pred, out);
}